// round 9
// baseline (speedup 1.0000x reference)
#include <cuda_runtime.h>
#include <cuda_bf16.h>

// ListMLE loss with tail term.
// Inputs: output f32 [B,V], target i32 [B], tails i32 [B,T], tail_len i32 [B]
// Output: f32 [B]
//
// Balanced decomposition: grid = 152*7 = 1064 CTAs (one exact wave), each CTA
// streams an EQUAL contiguous float4-share of the flattened [B*V] array
// (spans <= 2 rows) so every SM receives identical bytes. Per-row exp-sums
// combine via atomicAdd; the last-arriving CTA for a row (atomic-counter
// election, no spinning) finalizes that row IMMEDIATELY (inline in the loop,
// so a CTA elected for both of its rows finalizes both — R8 bug fix) and
// resets scratch to its zero-init state for graph-replay determinism.

#define THREADS 256
#define FULL    0xFFFFFFFFu
#define MAX_B   2048
#define NCTA    (152 * 7)

__device__ float        g_partial[MAX_B];   // zero-init; elected CTA restores 0
__device__ unsigned int g_count[MAX_B];     // zero-init; elected CTA restores 0

// Warp-parallel row finalize. Called by ALL threads of the elected CTA.
// es_sh/s_sh are [T] shared scratch.
__device__ __forceinline__
void finalize_row(int r, const float* __restrict__ output,
                  const int* __restrict__ target,
                  const int* __restrict__ tails,
                  const int* __restrict__ tail_len,
                  float* __restrict__ out,
                  int V, int T, float* es_sh, float* s_sh)
{
    const float* __restrict__ row = output + (size_t)r * (size_t)V;
    const int lane = threadIdx.x & 31;
    const int wid  = threadIdx.x >> 5;
    const int L = min(__ldg(tail_len + r), T);

    float tgt = 0.0f;
    if (threadIdx.x == 0) tgt = __ldg(row + __ldg(target + r));
    if (threadIdx.x < T) {
        const int t = threadIdx.x;
        float sv = 0.0f, ev = 0.0f;
        if (t < L) {
            sv = __ldg(row + __ldg(tails + r * T + t));
            ev = __expf(sv);
        }
        s_sh[t]  = sv;
        es_sh[t] = ev;
    }
    __syncthreads();

    if (wid == 0) {
        float total;
        if (lane == 0) {
            __threadfence();
            total = *((volatile float*)&g_partial[r]);
            // restore zero-init scratch for the next graph replay
            g_partial[r] = 0.0f;
            g_count[r]   = 0u;
        }
        total = __shfl_sync(FULL, total, 0);

        // tail elements: lane handles positions lane and lane+32
        float e0 = (lane      < L) ? es_sh[lane]      : 0.0f;
        float e1 = (lane + 32 < L) ? es_sh[lane + 32] : 0.0f;
        float s0 = (lane      < L) ? s_sh[lane]       : 0.0f;
        float s1 = (lane + 32 < L) ? s_sh[lane + 32]  : 0.0f;

        // inclusive SUFFIX scans (Kogge-Stone via shfl_down)
        float S1 = e1;
        #pragma unroll
        for (int o = 1; o < 32; o <<= 1) {
            float y = __shfl_down_sync(FULL, S1, o);
            if (lane + o < 32) S1 += y;
        }
        float S0 = e0;
        #pragma unroll
        for (int o = 1; o < 32; o <<= 1) {
            float y = __shfl_down_sync(FULL, S0, o);
            if (lane + o < 32) S0 += y;
        }
        const float sum_upper = __shfl_sync(FULL, S1, 0);
        S0 += sum_upper;                                  // global suffix sums
        const float sum_es = __shfl_sync(FULL, S0, 0);

        float ab = s0 + s1;
        #pragma unroll
        for (int o = 16; o > 0; o >>= 1)
            ab += __shfl_xor_sync(FULL, ab, o);

        const float tgt_b  = __shfl_sync(FULL, tgt, 0);
        const float others = total - __expf(tgt_b) - sum_es;

        float lg = 0.0f;
        if (lane      < L) lg += __logf(S0 + others);
        if (lane + 32 < L) lg += __logf(S1 + others);
        #pragma unroll
        for (int o = 16; o > 0; o >>= 1)
            lg += __shfl_xor_sync(FULL, lg, o);

        if (lane == 0) {
            const float log_pl    = tgt_b - __logf(total);
            const float tail_term = (L > 0) ? (ab - lg) : 0.0f;
            out[r] = -(log_pl + tail_term);
        }
    }
    __syncthreads();   // shared scratch reusable by the next row
}

__global__ __launch_bounds__(THREADS, 7)
void listmle_kernel(const float* __restrict__ output,
                    const int*   __restrict__ target,
                    const int*   __restrict__ tails,
                    const int*   __restrict__ tail_len,
                    float*       __restrict__ out,
                    int B, int V, int T, int share4, int nvec_row)
{
    const float4* __restrict__ out4 = reinterpret_cast<const float4*>(output);

    // this CTA's float4 range over the flattened array
    const int lo4 = blockIdx.x * share4;
    const int hi4 = min(lo4 + share4, B * nvec_row);
    if (lo4 >= hi4) return;

    __shared__ float warpsum[THREADS / 32];
    __shared__ int   sh_do;
    extern __shared__ float dyn_sh[];
    float* es_sh = dyn_sh;         // [T]
    float* s_sh  = dyn_sh + T;     // [T]

    const int lane = threadIdx.x & 31;
    const int wid  = threadIdx.x >> 5;

    const int r0 = lo4 / nvec_row;
    const int r1 = (hi4 - 1) / nvec_row;

    for (int r = r0; r <= r1; ++r) {
        const int seg_lo = max(lo4, r * nvec_row);
        const int seg_hi = min(hi4, (r + 1) * nvec_row);

        // ---- stream this row segment ----
        float acc = 0.0f;
        for (int i = seg_lo + (int)threadIdx.x; i < seg_hi; i += THREADS) {
            float4 v = __ldg(out4 + i);
            acc += (__expf(v.x) + __expf(v.y)) + (__expf(v.z) + __expf(v.w));
        }

        // ---- block reduce ----
        #pragma unroll
        for (int o = 16; o > 0; o >>= 1)
            acc += __shfl_xor_sync(FULL, acc, o);
        if (lane == 0) warpsum[wid] = acc;
        __syncthreads();

        // ---- combine + election (thread 0) ----
        if (threadIdx.x == 0) {
            float part = 0.0f;
            #pragma unroll
            for (int w = 0; w < THREADS / 32; ++w) part += warpsum[w];
            atomicAdd(&g_partial[r], part);
            __threadfence();
            // number of CTAs whose range intersects row r
            const int first_cta = (r * nvec_row) / share4;
            const int last_cta  = ((r + 1) * nvec_row - 1) / share4;
            const unsigned int need = (unsigned)(last_cta - first_cta + 1);
            const unsigned int old  = atomicAdd(&g_count[r], 1u);
            sh_do = (old == need - 1u) ? 1 : 0;
        }
        __syncthreads();

        // ---- if elected for THIS row, finalize it now (R8 fix) ----
        if (sh_do) {
            finalize_row(r, output, target, tails, tail_len, out,
                         V, T, es_sh, s_sh);
        }
        __syncthreads();
    }
}

extern "C" void kernel_launch(void* const* d_in, const int* in_sizes, int n_in,
                              void* d_out, int out_size)
{
    const float* output   = (const float*)d_in[0];
    const int*   target   = (const int*)  d_in[1];
    const int*   tails    = (const int*)  d_in[2];
    const int*   tail_len = (const int*)  d_in[3];
    float*       out      = (float*)      d_out;

    const int B = in_sizes[1];             // 1024
    const int V = in_sizes[0] / B;         // 50000 (multiple of 4)
    const int T = in_sizes[2] / B;         // 50

    const int nvec_row = V >> 2;           // 12500 float4 per row
    const int total4   = B * nvec_row;     // 12.8M
    const int share4   = (total4 + NCTA - 1) / NCTA;   // equal share per CTA

    const size_t shmem = 2 * (size_t)T * sizeof(float);
    listmle_kernel<<<NCTA, THREADS, shmem>>>(
        output, target, tails, tail_len, out, B, V, T, share4, nvec_row);
}

// round 10
// speedup vs baseline: 1.6687x; 1.6687x over previous
#include <cuda_runtime.h>
#include <cuda_bf16.h>

// ListMLE loss with tail term — converged kernel.
// Inputs: output f32 [B,V], target i32 [B], tails i32 [B,T], tail_len i32 [B]
// Output: f32 [B]
//
// Structure (established over 9 measured rounds):
//   - One CTA per row, 256 threads, single co-resident wave (7 CTAs/SM).
//   - Simple rolled float4 __ldg stream: measured at the device read ceiling
//     (~5.65 TB/s; DRAM busy ~97% of kernel lifetime). Chunking, work
//     stealing, policy splits, explicit batching, and balanced flat
//     decompositions all measured equal or worse.
//   - Tail gathers issued BEFORE the stream (latency hidden under bulk reads).
//   - Fully warp-parallel epilogue in warp 0 (Kogge-Stone suffix scan of
//     exp(tail), parallel logs, butterfly reductions).

#define THREADS 256
#define FULL    0xFFFFFFFFu

__global__ __launch_bounds__(THREADS, 7)
void listmle_tail_kernel(const float* __restrict__ output,
                         const int*   __restrict__ target,
                         const int*   __restrict__ tails,
                         const int*   __restrict__ tail_len,
                         float*       __restrict__ out,
                         int V, int T, int nvec, int has_rem)
{
    const int b = blockIdx.x;
    const float* __restrict__ row = output + (size_t)b * (size_t)V;

    extern __shared__ float dyn_sh[];
    float* es_sh = dyn_sh;           // [T] exp(tail scores)
    float* s_sh  = dyn_sh + T;       // [T] raw tail scores
    __shared__ float warpsum[THREADS / 32];

    const int L = min(__ldg(tail_len + b), T);

    // ---- early tail gathers: independent random loads, complete while the
    //      bulk stream below runs; no barrier needed until the epilogue ----
    float tgt = 0.0f;
    if (threadIdx.x == 0) tgt = __ldg(row + __ldg(target + b));
    if (threadIdx.x < T) {
        const int t = threadIdx.x;
        float sv = 0.0f, ev = 0.0f;
        if (t < L) {
            sv = __ldg(row + __ldg(tails + b * T + t));
            ev = __expf(sv);
        }
        s_sh[t]  = sv;
        es_sh[t] = ev;
    }

    // ---- streaming exp-sum (measured-optimal shape) ----
    float acc = 0.0f;
    const float4* __restrict__ row4 = reinterpret_cast<const float4*>(row);
    for (int i = threadIdx.x; i < nvec; i += THREADS) {
        float4 v = __ldg(row4 + i);
        acc += (__expf(v.x) + __expf(v.y)) + (__expf(v.z) + __expf(v.w));
    }
    if (has_rem) {   // V % 4 != 0 only; branch uniform across grid
        for (int j = (nvec << 2) + (int)threadIdx.x; j < V; j += THREADS)
            acc += __expf(__ldg(row + j));
    }

    // ---- per-warp reduce ----
    const int lane = threadIdx.x & 31;
    const int wid  = threadIdx.x >> 5;
    #pragma unroll
    for (int o = 16; o > 0; o >>= 1)
        acc += __shfl_xor_sync(FULL, acc, o);
    if (lane == 0) warpsum[wid] = acc;
    __syncthreads();

    // ---- warp 0: fully parallel epilogue ----
    if (wid == 0) {
        // total = sum of 8 warp partials (butterfly -> every lane)
        float t8 = (lane < THREADS / 32) ? warpsum[lane] : 0.0f;
        #pragma unroll
        for (int o = 16; o > 0; o >>= 1)
            t8 += __shfl_xor_sync(FULL, t8, o);
        const float total = t8;

        // tail elements: lane handles positions lane and lane+32
        float e0 = (lane      < L) ? es_sh[lane]      : 0.0f;
        float e1 = (lane + 32 < L) ? es_sh[lane + 32] : 0.0f;
        float s0 = (lane      < L) ? s_sh[lane]       : 0.0f;
        float s1 = (lane + 32 < L) ? s_sh[lane + 32]  : 0.0f;

        // inclusive SUFFIX scans within each 32-block (Kogge-Stone, shfl_down)
        float S1 = e1;
        #pragma unroll
        for (int o = 1; o < 32; o <<= 1) {
            float y = __shfl_down_sync(FULL, S1, o);
            if (lane + o < 32) S1 += y;
        }
        float S0 = e0;
        #pragma unroll
        for (int o = 1; o < 32; o <<= 1) {
            float y = __shfl_down_sync(FULL, S0, o);
            if (lane + o < 32) S0 += y;
        }
        const float sum_upper = __shfl_sync(FULL, S1, 0);  // sum of e[32..]
        S0 += sum_upper;                                   // global suffix sums
        const float sum_es = __shfl_sync(FULL, S0, 0);     // sum of all exp(s)

        // above = sum of raw tail scores
        float ab = s0 + s1;
        #pragma unroll
        for (int o = 16; o > 0; o >>= 1)
            ab += __shfl_xor_sync(FULL, ab, o);

        const float tgt_b  = __shfl_sync(FULL, tgt, 0);
        const float others = total - __expf(tgt_b) - sum_es;

        // below = sum over valid positions of log(suffix_sum + others)
        float lg = 0.0f;
        if (lane      < L) lg += __logf(S0 + others);
        if (lane + 32 < L) lg += __logf(S1 + others);
        #pragma unroll
        for (int o = 16; o > 0; o >>= 1)
            lg += __shfl_xor_sync(FULL, lg, o);

        if (lane == 0) {
            const float log_pl    = tgt_b - __logf(total);
            const float tail_term = (L > 0) ? (ab - lg) : 0.0f;
            out[b] = -(log_pl + tail_term);
        }
    }
}

extern "C" void kernel_launch(void* const* d_in, const int* in_sizes, int n_in,
                              void* d_out, int out_size)
{
    const float* output   = (const float*)d_in[0];
    const int*   target   = (const int*)  d_in[1];
    const int*   tails    = (const int*)  d_in[2];
    const int*   tail_len = (const int*)  d_in[3];
    float*       out      = (float*)      d_out;

    const int B = in_sizes[1];             // 1024
    const int V = in_sizes[0] / B;         // 50000
    const int T = in_sizes[2] / B;         // 50

    const int nvec    = V >> 2;
    const int has_rem = (V & 3) ? 1 : 0;

    const size_t shmem = 2 * (size_t)T * sizeof(float);
    listmle_tail_kernel<<<B, THREADS, shmem>>>(
        output, target, tails, tail_len, out, V, T, nvec, has_rem);
}